// round 2
// baseline (speedup 1.0000x reference)
#include <cuda_runtime.h>
#include <math.h>

#define Bb 256
#define Ll 200
#define Hh 768
#define Dd 64
#define Mm (Bb*Ll)          // 51200
#define G6 384
#define NS 6

#define OFF_PROBS 0
#define OFF_TTE   1536
#define OFF_CI    1792
#define OFF_HIST  3328

// ---------------- scratch (device globals; no allocation) ----------------
__device__ float g_gates[6][(size_t)Mm*Dd];   // pre-activated gates: si,sf,tz,so,decay,cb
__device__ float g_h[(size_t)Mm*Dd];          // hidden states (M,64)
__device__ float g_clast[Bb*Dd];
__device__ float g_gcur[4][Bb*Dd];            // current-step gates (si,sf,tz,so)
__device__ float g_hcur[Bb*Dd];
__device__ float g_tdir[Bb*G6];               // gelu(cls@Ws1+bs1)
__device__ float g_v[G6];                     // Wtime @ Wg[64:]
__device__ float g_beff[G6];                  // bg + btime @ Wg[64:]

// ---------------- math helpers ----------------
__device__ __forceinline__ float sigm_(float x){ return 1.f/(1.f+expf(-x)); }
__device__ __forceinline__ float softplus_(float x){
    return (x > 0.f) ? (x + log1pf(expf(-x))) : log1pf(expf(x));
}
__device__ __forceinline__ float gelu_(float x){
    return 0.5f * x * (1.f + erff(x * 0.70710678118654752440f));
}

// ---------------- K0: rank-1 time-feature folding ----------------
__global__ void prep_kernel(const float* __restrict__ Wtime, const float* __restrict__ btime,
                            const float* __restrict__ Wg, const float* __restrict__ bg)
{
    int j = threadIdx.x;
    if (j >= G6) return;
    float v = 0.f, bf = bg[j];
    #pragma unroll 8
    for (int d = 0; d < Dd; d++){
        float w = Wg[(size_t)(Dd + d) * G6 + j];
        v  += Wtime[d] * w;
        bf += btime[d] * w;
    }
    g_v[j] = v;
    g_beff[j] = bf;
}

// ---------------- K1: fused  E = X@We ; g = E@WgE + days*v + beff ; activations ----
// mode 0: grid 824. blocks [0,800): event rows -> g_gates (6 planes).
//                   blocks [800,824): direct-logits GEMM gelu(cls@Ws1+bs1) -> g_tdir.
// mode 1: grid 4.   cls rows -> g_gcur (4 planes), days = 0.
__global__ __launch_bounds__(256) void fused_main_kernel(
    const float* __restrict__ Xev, const float* __restrict__ days,
    const float* __restrict__ cls,
    const float* __restrict__ We,  const float* __restrict__ be,
    const float* __restrict__ Wg,
    const float* __restrict__ Ws1, const float* __restrict__ bs1,
    int mode)
{
    __shared__ float Xs[16][64];
    __shared__ float Wts[16][64];
    __shared__ float Es[64][65];
    __shared__ float CW[64][64];

    const int t  = threadIdx.x;
    const int tx = t & 15;
    const int ty = t >> 4;
    const int bx = blockIdx.x;

    const bool gelu_path = (mode == 0 && bx >= 800);

    const float* X; const float* W; int m0, c0, ldw;
    if (gelu_path){
        int idx = bx - 800;
        m0 = (idx & 3) * 64; c0 = (idx >> 2) * 64;
        X = cls; W = Ws1; ldw = G6;
    } else if (mode == 1){
        m0 = bx * 64; c0 = 0; X = cls; W = We; ldw = Dd;
    } else {
        m0 = bx * 64; c0 = 0; X = Xev; W = We; ldw = Dd;
    }

    float acc[4][4];
    #pragma unroll
    for (int i=0;i<4;i++)
        #pragma unroll
        for (int j=0;j<4;j++) acc[i][j] = 0.f;

    const int lrow = t >> 2, lk4 = (t & 3) * 4;
    const int wkr  = t >> 4, wnc = (t & 15) * 4;

    for (int k0 = 0; k0 < Hh; k0 += 16){
        float4 xv = *(const float4*)(X + (size_t)(m0 + lrow) * Hh + (k0 + lk4));
        Xs[lk4+0][lrow] = xv.x; Xs[lk4+1][lrow] = xv.y;
        Xs[lk4+2][lrow] = xv.z; Xs[lk4+3][lrow] = xv.w;
        float4 wv = *(const float4*)(W + (size_t)(k0 + wkr) * ldw + c0 + wnc);
        *(float4*)&Wts[wkr][wnc] = wv;
        __syncthreads();
        #pragma unroll
        for (int kk = 0; kk < 16; kk++){
            float a0 = Xs[kk][ty],    a1 = Xs[kk][ty+16],
                  a2 = Xs[kk][ty+32], a3 = Xs[kk][ty+48];
            float b0 = Wts[kk][tx],    b1 = Wts[kk][tx+16],
                  b2 = Wts[kk][tx+32], b3 = Wts[kk][tx+48];
            acc[0][0] += a0*b0; acc[0][1] += a0*b1; acc[0][2] += a0*b2; acc[0][3] += a0*b3;
            acc[1][0] += a1*b0; acc[1][1] += a1*b1; acc[1][2] += a1*b2; acc[1][3] += a1*b3;
            acc[2][0] += a2*b0; acc[2][1] += a2*b1; acc[2][2] += a2*b2; acc[2][3] += a2*b3;
            acc[3][0] += a3*b0; acc[3][1] += a3*b1; acc[3][2] += a3*b2; acc[3][3] += a3*b3;
        }
        __syncthreads();
    }

    if (gelu_path){
        #pragma unroll
        for (int i = 0; i < 4; i++)
            #pragma unroll
            for (int j = 0; j < 4; j++){
                int row = m0 + ty + 16*i, col = c0 + tx + 16*j;
                g_tdir[(size_t)row * G6 + col] = gelu_(acc[i][j] + bs1[col]);
            }
        return;
    }

    // ---- gates path: stage E (+be) into smem ----
    float be_[4];
    #pragma unroll
    for (int j = 0; j < 4; j++) be_[j] = be[tx + 16*j];
    #pragma unroll
    for (int i = 0; i < 4; i++)
        #pragma unroll
        for (int j = 0; j < 4; j++)
            Es[ty + 16*i][tx + 16*j] = acc[i][j] + be_[j];

    float dval[4], dtv[4];
    #pragma unroll
    for (int i = 0; i < 4; i++){
        dval[i] = (mode == 0) ? days[m0 + ty + 16*i] : 0.f;
        dtv[i]  = fmaxf(dval[i], 0.f);
    }
    __syncthreads();

    const int nch = (mode == 0) ? 6 : 4;
    for (int gc = 0; gc < nch; gc++){
        #pragma unroll
        for (int q = 0; q < 4; q++){
            int f = t + 256*q;
            int r = f >> 4, cc = (f & 15) * 4;
            *(float4*)&CW[r][cc] = *(const float4*)(Wg + (size_t)r * G6 + gc*64 + cc);
        }
        __syncthreads();

        float r4[4][4];
        #pragma unroll
        for (int i=0;i<4;i++)
            #pragma unroll
            for (int j=0;j<4;j++) r4[i][j] = 0.f;

        #pragma unroll 16
        for (int kk = 0; kk < 64; kk++){
            float a0 = Es[ty][kk],    a1 = Es[ty+16][kk],
                  a2 = Es[ty+32][kk], a3 = Es[ty+48][kk];
            float b0 = CW[kk][tx],    b1 = CW[kk][tx+16],
                  b2 = CW[kk][tx+32], b3 = CW[kk][tx+48];
            r4[0][0] += a0*b0; r4[0][1] += a0*b1; r4[0][2] += a0*b2; r4[0][3] += a0*b3;
            r4[1][0] += a1*b0; r4[1][1] += a1*b1; r4[1][2] += a1*b2; r4[1][3] += a1*b3;
            r4[2][0] += a2*b0; r4[2][1] += a2*b1; r4[2][2] += a2*b2; r4[2][3] += a2*b3;
            r4[3][0] += a3*b0; r4[3][1] += a3*b1; r4[3][2] += a3*b2; r4[3][3] += a3*b3;
        }

        #pragma unroll
        for (int i = 0; i < 4; i++)
            #pragma unroll
            for (int j = 0; j < 4; j++){
                int col = gc*64 + tx + 16*j;
                float g = r4[i][j] + dval[i]*g_v[col] + g_beff[col];
                float o;
                if      (gc == 2) o = tanhf(g);
                else if (gc == 4) o = expf(-softplus_(g) * dtv[i]);
                else if (gc == 5) o = g;
                else              o = sigm_(g);
                size_t oidx = (size_t)(m0 + ty + 16*i) * Dd + tx + 16*j;
                if (mode == 0) g_gates[gc][oidx] = o;
                else           g_gcur[gc][oidx]  = o;
            }
        __syncthreads();
    }
}

// ---------------- K2: CT-LSTM scan over L (chunked loads: MLP ~24) ----------------
__global__ void scan_kernel()
{
    const int b = blockIdx.x;
    const int d = threadIdx.x;            // 64 threads
    const size_t base = (size_t)b * Ll * Dd + d;
    const float* __restrict__ p0 = g_gates[0] + base;
    const float* __restrict__ p1 = g_gates[1] + base;
    const float* __restrict__ p2 = g_gates[2] + base;
    const float* __restrict__ p3 = g_gates[3] + base;
    const float* __restrict__ p4 = g_gates[4] + base;
    const float* __restrict__ p5 = g_gates[5] + base;
    float* __restrict__ ph = g_h + base;
    float c = 0.f;

    for (int l = 0; l < Ll; l += 4){
        size_t o0 = (size_t)l * Dd, o1 = o0 + Dd, o2 = o1 + Dd, o3 = o2 + Dd;
        float i0=p0[o0], f0=p1[o0], z0=p2[o0], oo0=p3[o0], e0=p4[o0], q0=p5[o0];
        float i1=p0[o1], f1=p1[o1], z1=p2[o1], oo1=p3[o1], e1=p4[o1], q1=p5[o1];
        float i2=p0[o2], f2=p1[o2], z2=p2[o2], oo2=p3[o2], e2=p4[o2], q2=p5[o2];
        float i3=p0[o3], f3=p1[o3], z3=p2[o3], oo3=p3[o3], e3=p4[o3], q3=p5[o3];

        c = f0*c + i0*z0; { float cd = q0 + (c - q0)*e0; ph[o0] = oo0 * tanhf(cd); }
        c = f1*c + i1*z1; { float cd = q1 + (c - q1)*e1; ph[o1] = oo1 * tanhf(cd); }
        c = f2*c + i2*z2; { float cd = q2 + (c - q2)*e2; ph[o2] = oo2 * tanhf(cd); }
        c = f3*c + i3*z3; { float cd = q3 + (c - q3)*e3; ph[o3] = oo3 * tanhf(cd); }
    }
    g_clast[b * Dd + d] = c;
}

// ---------------- K3: intensity MLP  softplus(gelu(h@Wi1+bi1)@Wi2+bi2) ----------------
// mode 0: hin = g_h (800 blocks);  mode 1: hin = g_hcur (4 blocks)
__global__ __launch_bounds__(256) void intensity_kernel(
    int mode,
    const float* __restrict__ Wi1, const float* __restrict__ bi1,
    const float* __restrict__ Wi2, const float* __restrict__ bi2,
    float* __restrict__ out)
{
    __shared__ float Hs[64][65];
    __shared__ float W1s[64][32];
    __shared__ float T1s[64][33];

    const float* hin = (mode == 0) ? g_h : g_hcur;
    const int t = threadIdx.x;
    const int r0 = blockIdx.x * 64;

    #pragma unroll
    for (int q = 0; q < 4; q++){
        int f = t + 256*q;
        int row = f >> 4, c4 = (f & 15) * 4;
        float4 v = *(const float4*)(hin + (size_t)(r0 + row) * Dd + c4);
        Hs[row][c4+0]=v.x; Hs[row][c4+1]=v.y; Hs[row][c4+2]=v.z; Hs[row][c4+3]=v.w;
    }
    #pragma unroll
    for (int q = 0; q < 2; q++){
        int f = t + 256*q;
        int k = f >> 3, c4 = (f & 7) * 4;
        *(float4*)&W1s[k][c4] = *(const float4*)(Wi1 + (size_t)k * 32 + c4);
    }
    __syncthreads();

    const int col = t & 31;
    const int rb  = t >> 5;       // warp id 0..7
    const float b1 = bi1[col];
    #pragma unroll
    for (int ii = 0; ii < 8; ii++){
        int row = rb * 8 + ii;
        float s = 0.f;
        #pragma unroll 16
        for (int k = 0; k < 64; k++) s += Hs[row][k] * W1s[k][col];
        T1s[row][col] = gelu_(s + b1);
    }
    __syncthreads();

    for (int off = t; off < 64 * NS; off += 256){
        int row = off / NS, c = off % NS;
        float s = bi2[c];
        #pragma unroll 8
        for (int k = 0; k < 32; k++) s += T1s[row][k] * Wi2[k * NS + c];
        out[(size_t)(r0 + row) * NS + c] = softplus_(s);
    }
}

// ---------------- K4: current cell update (dt=0 -> c_dec = c) ----------------
__global__ void curcell_kernel()
{
    int i = blockIdx.x * blockDim.x + threadIdx.x;   // Bb*Dd = 16384
    float c = g_gcur[1][i] * g_clast[i] + g_gcur[0][i] * g_gcur[2][i];
    g_hcur[i] = g_gcur[3][i] * tanhf(c);
}

// ---------------- K5: logits + softmax + tte ----------------
__global__ void final_kernel(const float* __restrict__ Ws2, const float* __restrict__ bs2,
                             const float* __restrict__ Wq1, const float* __restrict__ bq1,
                             const float* __restrict__ Wq2, const float* __restrict__ bq2,
                             float* __restrict__ dout)
{
    int b = threadIdx.x;   // 256 threads, one row each

    // direct logits: t_dir[b] @ Ws2 + bs2
    float lg[NS];
    #pragma unroll
    for (int c = 0; c < NS; c++) lg[c] = bs2[c];
    const float* tr = g_tdir + (size_t)b * G6;
    #pragma unroll 4
    for (int k = 0; k < G6; k++){
        float tv = tr[k];
        #pragma unroll
        for (int c = 0; c < NS; c++) lg[c] += tv * Ws2[k * NS + c];
    }

    // + log(current_intensity), softmax
    const float* ci = dout + OFF_CI + (size_t)b * NS;
    float li[NS], mx = -1e30f;
    #pragma unroll
    for (int c = 0; c < NS; c++){ li[c] = lg[c] + logf(ci[c]); mx = fmaxf(mx, li[c]); }
    float den = 0.f, ex[NS];
    #pragma unroll
    for (int c = 0; c < NS; c++){ ex[c] = expf(li[c] - mx); den += ex[c]; }
    float inv = 1.f / den;
    #pragma unroll
    for (int c = 0; c < NS; c++) dout[OFF_PROBS + (size_t)b * NS + c] = ex[c] * inv;

    // tte = softplus(gelu(h@Wq1+bq1)@Wq2+bq2)
    float t2[32];
    #pragma unroll
    for (int c = 0; c < 32; c++) t2[c] = bq1[c];
    const float* hr = g_hcur + (size_t)b * Dd;
    #pragma unroll 4
    for (int k = 0; k < Dd; k++){
        float hv = hr[k];
        #pragma unroll
        for (int c = 0; c < 32; c++) t2[c] += hv * Wq1[k * 32 + c];
    }
    float q = bq2[0];
    #pragma unroll
    for (int c = 0; c < 32; c++) q += gelu_(t2[c]) * Wq2[c];
    dout[OFF_TTE + b] = softplus_(q);
}

// ---------------- launch ----------------
extern "C" void kernel_launch(void* const* d_in, const int* in_sizes, int n_in,
                              void* d_out, int out_size)
{
    const float* cls   = (const float*)d_in[0];
    const float* ev    = (const float*)d_in[1];
    const float* days  = (const float*)d_in[2];
    const float* We    = (const float*)d_in[3];
    const float* be    = (const float*)d_in[4];
    const float* Wtime = (const float*)d_in[5];
    const float* btime = (const float*)d_in[6];
    const float* Wg    = (const float*)d_in[7];
    const float* bg    = (const float*)d_in[8];
    const float* Wi1   = (const float*)d_in[9];
    const float* bi1   = (const float*)d_in[10];
    const float* Wi2   = (const float*)d_in[11];
    const float* bi2   = (const float*)d_in[12];
    const float* Ws1   = (const float*)d_in[13];
    const float* bs1   = (const float*)d_in[14];
    const float* Ws2   = (const float*)d_in[15];
    const float* bs2   = (const float*)d_in[16];
    const float* Wq1   = (const float*)d_in[17];
    const float* bq1   = (const float*)d_in[18];
    const float* Wq2   = (const float*)d_in[19];
    const float* bq2   = (const float*)d_in[20];
    float* dout = (float*)d_out;

    prep_kernel<<<1, G6>>>(Wtime, btime, Wg, bg);

    // 800 gate blocks + 24 direct-logit blocks riding the same wave
    fused_main_kernel<<<824, 256>>>(ev, days, cls, We, be, Wg, Ws1, bs1, 0);

    scan_kernel<<<Bb, Dd>>>();

    intensity_kernel<<<Mm/64, 256>>>(0, Wi1, bi1, Wi2, bi2, dout + OFF_HIST);

    fused_main_kernel<<<Bb/64, 256>>>(ev, nullptr, cls, We, be, Wg, Ws1, bs1, 1);
    curcell_kernel<<<32, 512>>>();

    intensity_kernel<<<Bb/64, 256>>>(1, Wi1, bi1, Wi2, bi2, dout + OFF_CI);

    final_kernel<<<1, Bb>>>(Ws2, bs2, Wq1, bq1, Wq2, bq2, dout);
}

// round 4
// speedup vs baseline: 1.2667x; 1.2667x over previous
#include <cuda_runtime.h>
#include <math.h>

#define Bb 256
#define Ll 200
#define Hh 768
#define Dd 64
#define Mm (Bb*Ll)          // 51200
#define G6 384
#define NS 6

#define OFF_PROBS 0
#define OFF_TTE   1536
#define OFF_CI    1792
#define OFF_HIST  3328

// ---------------- scratch (device globals; no allocation) ----------------
__device__ __align__(16) float g_gates[6][(size_t)Mm*Dd];
__device__ __align__(16) float g_h[(size_t)Mm*Dd];
__device__ __align__(16) float g_clast[Bb*Dd];
__device__ __align__(16) float g_gcur[4][Bb*Dd];
__device__ __align__(16) float g_hcur[Bb*Dd];
__device__ __align__(16) float g_ecur[Bb*Dd];
__device__ __align__(16) float g_tdirT[(size_t)G6*Bb];   // transposed: [col][b]
__device__ __align__(16) float g_v[G6];
__device__ __align__(16) float g_beff[G6];

// ---------------- math helpers ----------------
__device__ __forceinline__ float sigm_(float x){ return 1.f/(1.f+expf(-x)); }
__device__ __forceinline__ float softplus_(float x){
    return (x > 0.f) ? (x + log1pf(expf(-x))) : log1pf(expf(x));
}
__device__ __forceinline__ float gelu_(float x){
    return 0.5f * x * (1.f + erff(x * 0.70710678118654752440f));
}

// ---------------- K0: rank-1 time-feature folding ----------------
__global__ void prep_kernel(const float* __restrict__ Wtime, const float* __restrict__ btime,
                            const float* __restrict__ Wg, const float* __restrict__ bg)
{
    int j = threadIdx.x;
    if (j >= G6) return;
    float v = 0.f, bf = bg[j];
    #pragma unroll 8
    for (int d = 0; d < Dd; d++){
        float w = Wg[(size_t)(Dd + d) * G6 + j];
        v  += Wtime[d] * w;
        bf += btime[d] * w;
    }
    g_v[j] = v;
    g_beff[j] = bf;
}

// ---------------- K1: fused  E = X@We ; g = E@WgE + days*v + beff ; activations ----
// grid 412: blocks [0,400): event rows, tile 128x64 -> g_gates (6 planes).
//           blocks [400,412): gelu(cls@Ws1+bs1) 128x64 tiles -> g_tdirT.
// smem: [0,3072) k-tile double buffers (Xs [2][128][8], Wts [2][8][64]);
//       CW [64][64] aliases [0,4096); Es [128][64] at [4096,12288). 49152 B total.
#define FMA4(acc0,acc1,acc2,acc3) \
    acc0 = fmaf(a.x,b0.x,fmaf(a.y,b1.x,fmaf(a.z,b2.x,fmaf(a.w,b3.x,acc0)))); \
    acc1 = fmaf(a.x,b0.y,fmaf(a.y,b1.y,fmaf(a.z,b2.y,fmaf(a.w,b3.y,acc1)))); \
    acc2 = fmaf(a.x,b0.z,fmaf(a.y,b1.z,fmaf(a.z,b2.z,fmaf(a.w,b3.z,acc2)))); \
    acc3 = fmaf(a.x,b0.w,fmaf(a.y,b1.w,fmaf(a.z,b2.w,fmaf(a.w,b3.w,acc3))));

__global__ void __launch_bounds__(256, 2) fused_main_kernel(
    const float* __restrict__ Xev, const float* __restrict__ days,
    const float* __restrict__ cls,
    const float* __restrict__ We,  const float* __restrict__ be,
    const float* __restrict__ Wg,
    const float* __restrict__ Ws1, const float* __restrict__ bs1)
{
    extern __shared__ float sm[];
    float* Xs  = sm;          // [2][128][8]   2048 floats
    float* Wts = sm + 2048;   // [2][8][64]    1024 floats
    float* CW  = sm;          // alias: [64][64] 4096 floats
    float* Es  = sm + 4096;   // [128][64]     8192 floats

    const int t  = threadIdx.x;
    const int tx = t & 15;
    const int ty = t >> 4;
    const int bx = blockIdx.x;
    const bool gp = (bx >= 400);

    const float* X; const float* W; int m0, c0, ldw;
    if (gp){ int idx = bx - 400; m0 = (idx & 1) * 128; c0 = (idx >> 1) * 64; X = cls; W = Ws1; ldw = G6; }
    else   { m0 = bx * 128; c0 = 0; X = Xev; W = We; ldw = Dd; }

    float acc[8][4];
    #pragma unroll
    for (int i=0;i<8;i++){ acc[i][0]=0.f; acc[i][1]=0.f; acc[i][2]=0.f; acc[i][3]=0.f; }

    // loaders: Xs tile 128x8 -> 256 float4 (one per thread); Wts 8x64 -> 128 float4
    const int arow = t >> 1,  ac4 = (t & 1) * 4;
    const int brow = t >> 4,  bc4 = (t & 15) * 4;   // brow valid when t < 128

    const float* Xr = X + (size_t)(m0 + arow) * Hh + ac4;
    const float* Wr = W + (size_t)brow * ldw + c0 + bc4;

    // prologue: tile 0
    float4 xa = *(const float4*)(Xr);
    float4 wb;
    if (t < 128) wb = *(const float4*)(Wr);
    *(float4*)&Xs[arow*8 + ac4] = xa;
    if (t < 128) *(float4*)&Wts[brow*64 + bc4] = wb;
    __syncthreads();

    const int NT = Hh / 8;   // 96 k-tiles
    for (int kt = 0; kt < NT; kt++){
        const int cur = kt & 1, nxt = cur ^ 1;
        if (kt < NT - 1){
            int k0 = 8*(kt+1);
            xa = *(const float4*)(Xr + k0);
            if (t < 128) wb = *(const float4*)(Wr + (size_t)k0 * ldw);
        }
        const float* Xc = Xs + cur*1024;
        const float* Wc = Wts + cur*512;
        #pragma unroll
        for (int kc = 0; kc < 2; kc++){
            float4 b0 = *(const float4*)&Wc[(4*kc+0)*64 + 4*tx];
            float4 b1 = *(const float4*)&Wc[(4*kc+1)*64 + 4*tx];
            float4 b2 = *(const float4*)&Wc[(4*kc+2)*64 + 4*tx];
            float4 b3 = *(const float4*)&Wc[(4*kc+3)*64 + 4*tx];
            #pragma unroll
            for (int i = 0; i < 8; i++){
                float4 a = *(const float4*)&Xc[(ty+16*i)*8 + 4*kc];
                FMA4(acc[i][0], acc[i][1], acc[i][2], acc[i][3])
            }
        }
        if (kt < NT - 1){
            float* Xn = Xs + nxt*1024;
            float* Wn = Wts + nxt*512;
            *(float4*)&Xn[arow*8 + ac4] = xa;
            if (t < 128) *(float4*)&Wn[brow*64 + bc4] = wb;
        }
        __syncthreads();
    }

    if (gp){
        #pragma unroll
        for (int i = 0; i < 8; i++){
            int row = m0 + ty + 16*i;
            #pragma unroll
            for (int j = 0; j < 4; j++){
                int col = c0 + 4*tx + j;
                g_tdirT[(size_t)col * Bb + row] = gelu_(acc[i][j] + bs1[col]);
            }
        }
        return;
    }

    // stage E (+be) into smem; capture days
    float4 be4 = *(const float4*)(be + 4*tx);
    float dval[8], dtv[8];
    #pragma unroll
    for (int i = 0; i < 8; i++){
        float4 v = make_float4(acc[i][0]+be4.x, acc[i][1]+be4.y, acc[i][2]+be4.z, acc[i][3]+be4.w);
        *(float4*)&Es[(ty+16*i)*64 + 4*tx] = v;
        dval[i] = days[m0 + ty + 16*i];
        dtv[i]  = fmaxf(dval[i], 0.f);
    }
    __syncthreads();

    for (int gc = 0; gc < 6; gc++){
        #pragma unroll
        for (int q = 0; q < 4; q++){
            int f = t + 256*q;
            int r = f >> 4, c4 = (f & 15) * 4;
            *(float4*)&CW[r*64 + c4] = *(const float4*)(Wg + (size_t)r * G6 + gc*64 + c4);
        }
        __syncthreads();

        float vv[4], bf[4];
        #pragma unroll
        for (int j = 0; j < 4; j++){
            vv[j] = g_v[gc*64 + 4*tx + j];
            bf[j] = g_beff[gc*64 + 4*tx + j];
        }

        float r8[8][4];
        #pragma unroll
        for (int i=0;i<8;i++){ r8[i][0]=0.f; r8[i][1]=0.f; r8[i][2]=0.f; r8[i][3]=0.f; }

        #pragma unroll 4
        for (int kc = 0; kc < 16; kc++){
            float4 b0 = *(const float4*)&CW[(4*kc+0)*64 + 4*tx];
            float4 b1 = *(const float4*)&CW[(4*kc+1)*64 + 4*tx];
            float4 b2 = *(const float4*)&CW[(4*kc+2)*64 + 4*tx];
            float4 b3 = *(const float4*)&CW[(4*kc+3)*64 + 4*tx];
            #pragma unroll
            for (int i = 0; i < 8; i++){
                float4 a = *(const float4*)&Es[(ty+16*i)*64 + 4*kc];
                FMA4(r8[i][0], r8[i][1], r8[i][2], r8[i][3])
            }
        }

        #pragma unroll
        for (int i = 0; i < 8; i++){
            float gv[4], ov[4];
            #pragma unroll
            for (int j = 0; j < 4; j++)
                gv[j] = r8[i][j] + dval[i]*vv[j] + bf[j];
            if (gc == 2){
                #pragma unroll
                for (int j = 0; j < 4; j++) ov[j] = tanhf(gv[j]);
            } else if (gc == 4){
                #pragma unroll
                for (int j = 0; j < 4; j++) ov[j] = expf(-softplus_(gv[j]) * dtv[i]);
            } else if (gc == 5){
                #pragma unroll
                for (int j = 0; j < 4; j++) ov[j] = gv[j];
            } else {
                #pragma unroll
                for (int j = 0; j < 4; j++) ov[j] = sigm_(gv[j]);
            }
            float4 o4 = make_float4(ov[0], ov[1], ov[2], ov[3]);
            *(float4*)(g_gates[gc] + (size_t)(m0 + ty + 16*i) * Dd + 4*tx) = o4;
        }
        __syncthreads();
    }
}

// ---------------- K2: CT-LSTM scan over L (chunked loads: MLP ~24) ----------------
__global__ void scan_kernel()
{
    const int b = blockIdx.x;
    const int d = threadIdx.x;            // 64 threads
    const size_t base = (size_t)b * Ll * Dd + d;
    const float* __restrict__ p0 = g_gates[0] + base;
    const float* __restrict__ p1 = g_gates[1] + base;
    const float* __restrict__ p2 = g_gates[2] + base;
    const float* __restrict__ p3 = g_gates[3] + base;
    const float* __restrict__ p4 = g_gates[4] + base;
    const float* __restrict__ p5 = g_gates[5] + base;
    float* __restrict__ ph = g_h + base;
    float c = 0.f;

    for (int l = 0; l < Ll; l += 4){
        size_t o0 = (size_t)l * Dd, o1 = o0 + Dd, o2 = o1 + Dd, o3 = o2 + Dd;
        float i0=p0[o0], f0=p1[o0], z0=p2[o0], oo0=p3[o0], e0=p4[o0], q0=p5[o0];
        float i1=p0[o1], f1=p1[o1], z1=p2[o1], oo1=p3[o1], e1=p4[o1], q1=p5[o1];
        float i2=p0[o2], f2=p1[o2], z2=p2[o2], oo2=p3[o2], e2=p4[o2], q2=p5[o2];
        float i3=p0[o3], f3=p1[o3], z3=p2[o3], oo3=p3[o3], e3=p4[o3], q3=p5[o3];

        c = f0*c + i0*z0; { float cd = q0 + (c - q0)*e0; ph[o0] = oo0 * tanhf(cd); }
        c = f1*c + i1*z1; { float cd = q1 + (c - q1)*e1; ph[o1] = oo1 * tanhf(cd); }
        c = f2*c + i2*z2; { float cd = q2 + (c - q2)*e2; ph[o2] = oo2 * tanhf(cd); }
        c = f3*c + i3*z3; { float cd = q3 + (c - q3)*e3; ph[o3] = oo3 * tanhf(cd); }
    }
    g_clast[b * Dd + d] = c;
}

// ---------------- K3: intensity MLP  softplus(gelu(h@Wi1+bi1)@Wi2+bi2) ----------------
__global__ __launch_bounds__(256) void intensity_kernel(
    int mode,
    const float* __restrict__ Wi1, const float* __restrict__ bi1,
    const float* __restrict__ Wi2, const float* __restrict__ bi2,
    float* __restrict__ out)
{
    __shared__ __align__(16) float Hs[64][68];
    __shared__ __align__(16) float W1c[16][32][4];   // [kchunk][col][4k]
    __shared__ float T1s[64][33];

    const float* hin = (mode == 0) ? g_h : g_hcur;
    const int t = threadIdx.x;
    const int r0 = blockIdx.x * 64;

    #pragma unroll
    for (int q = 0; q < 4; q++){
        int f = t + 256*q;
        int row = f >> 4, c4 = (f & 15) * 4;
        *(float4*)&Hs[row][c4] = *(const float4*)(hin + (size_t)(r0 + row) * Dd + c4);
    }
    #pragma unroll
    for (int q = 0; q < 2; q++){
        int f = t + 256*q;
        int k = f >> 3, c4 = (f & 7) * 4;
        float4 w = *(const float4*)(Wi1 + (size_t)k * 32 + c4);
        W1c[k>>2][c4+0][k&3] = w.x;
        W1c[k>>2][c4+1][k&3] = w.y;
        W1c[k>>2][c4+2][k&3] = w.z;
        W1c[k>>2][c4+3][k&3] = w.w;
    }
    __syncthreads();

    const int col = t & 31;
    const int rb  = t >> 5;
    float s[8] = {0,0,0,0,0,0,0,0};
    #pragma unroll
    for (int kc = 0; kc < 16; kc++){
        float4 b = *(const float4*)&W1c[kc][col][0];
        #pragma unroll
        for (int i = 0; i < 8; i++){
            float4 a = *(const float4*)&Hs[rb*8 + i][4*kc];
            s[i] = fmaf(a.x,b.x,fmaf(a.y,b.y,fmaf(a.z,b.z,fmaf(a.w,b.w,s[i]))));
        }
    }
    const float b1 = bi1[col];
    #pragma unroll
    for (int i = 0; i < 8; i++)
        T1s[rb*8 + i][col] = gelu_(s[i] + b1);
    __syncthreads();

    for (int off = t; off < 64 * NS; off += 256){
        int row = off / NS, c = off % NS;
        float ss = bi2[c];
        #pragma unroll 8
        for (int k = 0; k < 32; k++) ss += T1s[row][k] * Wi2[k * NS + c];
        out[(size_t)(r0 + row) * NS + c] = softplus_(ss);
    }
}

// ---------------- K4a: E_cur = cls@We + be ----------------
__global__ void ecur_kernel(const float* __restrict__ cls,
                            const float* __restrict__ We, const float* __restrict__ be)
{
    int b = blockIdx.x * 4 + (threadIdx.x >> 6);
    int d = threadIdx.x & 63;
    float s = be[d];
    const float* xr = cls + (size_t)b * Hh;
    #pragma unroll 4
    for (int k = 0; k < Hh; k += 4){
        float4 x = *(const float4*)(xr + k);
        s = fmaf(x.x, We[(size_t)(k+0)*Dd + d], s);
        s = fmaf(x.y, We[(size_t)(k+1)*Dd + d], s);
        s = fmaf(x.z, We[(size_t)(k+2)*Dd + d], s);
        s = fmaf(x.w, We[(size_t)(k+3)*Dd + d], s);
    }
    g_ecur[b * Dd + d] = s;
}

// ---------------- K4b: current-step gates (dt=0, channels i,f,z,o) ----------------
__global__ void gcur_kernel(const float* __restrict__ Wg)
{
    __shared__ float Er[64];
    int b = blockIdx.x, col = threadIdx.x;   // 256 threads -> channels 0..3
    if (col < 64) Er[col] = g_ecur[b * Dd + col];
    __syncthreads();
    float s = g_beff[col];
    #pragma unroll 8
    for (int k = 0; k < 64; k++) s = fmaf(Er[k], Wg[(size_t)k * G6 + col], s);
    int ch = col >> 6, cc = col & 63;
    float o = (ch == 2) ? tanhf(s) : sigm_(s);
    g_gcur[ch][b * Dd + cc] = o;
}

// ---------------- K4c: current cell update (dt=0 -> c_dec = c) ----------------
__global__ void curcell_kernel()
{
    int i = blockIdx.x * blockDim.x + threadIdx.x;   // Bb*Dd = 16384
    float c = g_gcur[1][i] * g_clast[i] + g_gcur[0][i] * g_gcur[2][i];
    g_hcur[i] = g_gcur[3][i] * tanhf(c);
}

// ---------------- K5: logits + softmax + tte ----------------
__global__ void final_kernel(const float* __restrict__ Ws2, const float* __restrict__ bs2,
                             const float* __restrict__ Wq1, const float* __restrict__ bq1,
                             const float* __restrict__ Wq2, const float* __restrict__ bq2,
                             float* __restrict__ dout)
{
    __shared__ float sW2[G6 * NS];     // 2304
    __shared__ float sQ1[Dd * 32];     // 2048
    int b = threadIdx.x;               // 256 threads, one row each

    for (int i = b; i < G6 * NS; i += 256) sW2[i] = Ws2[i];
    for (int i = b; i < Dd * 32; i += 256) sQ1[i] = Wq1[i];
    __syncthreads();

    float lg[NS];
    #pragma unroll
    for (int c = 0; c < NS; c++) lg[c] = bs2[c];
    #pragma unroll 4
    for (int k = 0; k < G6; k++){
        float tv = g_tdirT[(size_t)k * Bb + b];
        #pragma unroll
        for (int c = 0; c < NS; c++) lg[c] += tv * sW2[k * NS + c];
    }

    const float* ci = dout + OFF_CI + (size_t)b * NS;
    float li[NS], mx = -1e30f;
    #pragma unroll
    for (int c = 0; c < NS; c++){ li[c] = lg[c] + logf(ci[c]); mx = fmaxf(mx, li[c]); }
    float den = 0.f, ex[NS];
    #pragma unroll
    for (int c = 0; c < NS; c++){ ex[c] = expf(li[c] - mx); den += ex[c]; }
    float inv = 1.f / den;
    #pragma unroll
    for (int c = 0; c < NS; c++) dout[OFF_PROBS + (size_t)b * NS + c] = ex[c] * inv;

    float t2[32];
    #pragma unroll
    for (int c = 0; c < 32; c++) t2[c] = bq1[c];
    const float* hr = g_hcur + (size_t)b * Dd;
    #pragma unroll 4
    for (int k = 0; k < Dd; k++){
        float hv = hr[k];
        #pragma unroll
        for (int c = 0; c < 32; c++) t2[c] += hv * sQ1[k * 32 + c];
    }
    float q = bq2[0];
    #pragma unroll
    for (int c = 0; c < 32; c++) q += gelu_(t2[c]) * Wq2[c];
    dout[OFF_TTE + b] = softplus_(q);
}

// ---------------- launch ----------------
extern "C" void kernel_launch(void* const* d_in, const int* in_sizes, int n_in,
                              void* d_out, int out_size)
{
    const float* cls   = (const float*)d_in[0];
    const float* ev    = (const float*)d_in[1];
    const float* days  = (const float*)d_in[2];
    const float* We    = (const float*)d_in[3];
    const float* be    = (const float*)d_in[4];
    const float* Wtime = (const float*)d_in[5];
    const float* btime = (const float*)d_in[6];
    const float* Wg    = (const float*)d_in[7];
    const float* bg    = (const float*)d_in[8];
    const float* Wi1   = (const float*)d_in[9];
    const float* bi1   = (const float*)d_in[10];
    const float* Wi2   = (const float*)d_in[11];
    const float* bi2   = (const float*)d_in[12];
    const float* Ws1   = (const float*)d_in[13];
    const float* bs1   = (const float*)d_in[14];
    const float* Ws2   = (const float*)d_in[15];
    const float* bs2   = (const float*)d_in[16];
    const float* Wq1   = (const float*)d_in[17];
    const float* bq1   = (const float*)d_in[18];
    const float* Wq2   = (const float*)d_in[19];
    const float* bq2   = (const float*)d_in[20];
    float* dout = (float*)d_out;

    const int SMEM = 12288 * 4;   // 49152 B dynamic smem — within default 48KB limit

    prep_kernel<<<1, G6>>>(Wtime, btime, Wg, bg);

    // 400 gate blocks + 12 direct-logit blocks in one grid
    fused_main_kernel<<<412, 256, SMEM>>>(ev, days, cls, We, be, Wg, Ws1, bs1);

    scan_kernel<<<Bb, Dd>>>();

    intensity_kernel<<<Mm/64, 256>>>(0, Wi1, bi1, Wi2, bi2, dout + OFF_HIST);

    ecur_kernel<<<Bb/4, 256>>>(cls, We, be);
    gcur_kernel<<<Bb, 256>>>(Wg);
    curcell_kernel<<<32, 512>>>();

    intensity_kernel<<<Bb/64, 256>>>(1, Wi1, bi1, Wi2, bi2, dout + OFF_CI);

    final_kernel<<<1, Bb>>>(Ws2, bs2, Wq1, bq1, Wq2, bq2, dout);
}